// round 4
// baseline (speedup 1.0000x reference)
#include <cuda_runtime.h>

// MegaNeRF MoE head: N=131072 points, E=8 experts, MLP 90 -> 256 -> 4,
// inverse-distance expert gating with margin cutoff.
//
// Round 3: fp32x2 packed-FMA kernel (fma.rn.f32x2 — Blackwell packed fp32,
// 2 MACs per fma-pipe slot, full fp32 precision).
//   - K dimension repacked in smem as (2k, 2k+1) pairs so each LDS.128
//     (read as ulonglong2) yields two ready f32x2 operands — no packing in
//     the hot loop.
//   - feat smem reads are warp-uniform (broadcast) -> ~free; W1 reads are
//     4 LDS.128/kp/thread -> smem demand is half the FFMA2 pipe demand.
//   - Per-thread tile: 8 points x 8 hidden, accumulators are f32x2 pairs
//     (even-k / odd-k partial sums, summed in the epilogue).

#define NPTS  131072
#define NEXP  8
#define DIN   90
#define HID   256
#define DOUTS 4
#define XCOLS 93
#define KP    (DIN / 2)          // 45 k-pairs

#define BM       64
#define NTHREADS 256
#define FS2      72              // feat row stride in float2 units (144 floats)

// smem layout (floats)
#define OFF_FEAT 0                                   // [KP][FS2*2] pair-interleaved
#define OFF_W1   (OFF_FEAT + KP * FS2 * 2)           // 6480 ; [KP][512] pair-interleaved
#define OFF_XYZ  (OFF_W1 + KP * HID * 2)             // +23040
#define OFF_WGT  (OFF_XYZ + BM * 4)                  // +256
#define OFF_B1   (OFF_WGT + BM * NEXP)               // +512
#define OFF_W2   (OFF_B1 + HID)                      // +256
#define SMEM_FLOATS (OFF_W2 + HID * DOUTS)           // +1024 = 31568 floats
#define SMEM_BYTES  (SMEM_FLOATS * 4)                // 126272 B

#define FFMA2(acc, a, b) \
    asm("fma.rn.f32x2 %0, %1, %2, %0;" : "+l"(acc) : "l"(a), "l"(b))

static __global__ void __launch_bounds__(NTHREADS, 1)
meganerf_kernel(const float* __restrict__ x,
                const float* __restrict__ cent,
                const float* __restrict__ W1,
                const float* __restrict__ b1,
                const float* __restrict__ W2,
                const float* __restrict__ b2,
                float* __restrict__ out)
{
    extern __shared__ float sm[];
    float* feat_s = sm + OFF_FEAT;   // feat_s[kp*144 + p*2 + parity]
    float* w1_s   = sm + OFF_W1;     // w1_s[kp*512 + j*2 + parity]
    float* xyz_s  = sm + OFF_XYZ;    // [BM][4]
    float* wgt_s  = sm + OFF_WGT;    // [BM][NEXP]
    float* b1_s   = sm + OFF_B1;     // [HID]
    float* w2_s   = sm + OFF_W2;     // [HID][4]

    const int tid  = threadIdx.x;
    const int lane = tid & 31;
    const int warp = tid >> 5;                 // 0..7  -> point group
    const long n0  = (long)blockIdx.x * BM;

    // ---- load x tile, coalesced; split xyz / pair-interleaved feat ----
    const float* xt = x + n0 * XCOLS;
    for (int i = tid; i < BM * XCOLS; i += NTHREADS) {
        float v = xt[i];
        int p = i / XCOLS;
        int c = i - p * XCOLS;
        if (c < 3) {
            xyz_s[p * 4 + c] = v;
        } else {
            int k = c - 3;                      // 0..89
            feat_s[(k >> 1) * (FS2 * 2) + p * 2 + (k & 1)] = v;
        }
    }
    __syncthreads();

    // ---- per-point gating weights (one thread per point) ----
    if (tid < BM) {
        float px = xyz_s[tid * 4 + 0];
        float py = xyz_s[tid * 4 + 1];
        float pz = xyz_s[tid * 4 + 2];
        float d[NEXP];
        float mind = 3.402823466e38f;
        #pragma unroll
        for (int e = 0; e < NEXP; e++) {
            float dx = px - cent[e * 3 + 0];
            float dy = py - cent[e * 3 + 1];
            float dz = pz - cent[e * 3 + 2];
            float dd = sqrtf(dx * dx + dy * dy + dz * dz);
            d[e] = dd;
            mind = fminf(mind, dd);
        }
        float thr = 2.0f * mind;
        float inv[NEXP];
        float s = 0.0f;
        #pragma unroll
        for (int e = 0; e < NEXP; e++) {
            float iv = (d[e] > thr) ? 0.0f : 1.0f / (d[e] + 1e-8f);
            inv[e] = iv;
            s += iv;
        }
        float rs = 1.0f / s;
        #pragma unroll
        for (int e = 0; e < NEXP; e++) wgt_s[tid * NEXP + e] = inv[e] * rs;
    }

    const int p0 = warp * 8;       // this warp's 8 points
    const int j0 = lane * 4;       // hidden cols: [j0, j0+4) and [128+j0, ...)

    float acc_out[8][4];
    #pragma unroll
    for (int p = 0; p < 8; p++)
        #pragma unroll
        for (int o = 0; o < 4; o++) acc_out[p][o] = 0.0f;

    for (int e = 0; e < NEXP; e++) {
        __syncthreads();   // protect w1_s/b1_s/w2_s readers of previous iter
        // stage W1[e] pair-interleaved: w1_s[kp][2*j + (row&1)]
        const float* w1g = W1 + (size_t)e * DIN * HID;
        for (int idx = tid * 4; idx < DIN * HID; idx += NTHREADS * 4) {
            float4 v = *(const float4*)(w1g + idx);
            int r  = idx >> 8;           // row 0..89
            int c  = idx & 255;          // col, multiple of 4
            float* dst = w1_s + (r >> 1) * (HID * 2) + 2 * c + (r & 1);
            dst[0] = v.x; dst[2] = v.y; dst[4] = v.z; dst[6] = v.w;
        }
        for (int i = tid; i < HID; i += NTHREADS)
            b1_s[i] = b1[e * HID + i];
        for (int i = tid; i < HID * DOUTS; i += NTHREADS)
            w2_s[i] = W2[e * HID * DOUTS + i];
        __syncthreads();

        // ---- main GEMM fragment: 8 points x 8 hidden, K=90 as 45 pairs ----
        unsigned long long acc[8][8];
        #pragma unroll
        for (int p = 0; p < 8; p++)
            #pragma unroll
            for (int j = 0; j < 8; j++) acc[p][j] = 0ULL;

        const float* frow = feat_s + p0 * 2;
        const float* wrow = w1_s + 2 * j0;
        #pragma unroll 3
        for (int kp = 0; kp < KP; kp++, frow += FS2 * 2, wrow += HID * 2) {
            ulonglong2 fa = *(const ulonglong2*)(frow);
            ulonglong2 fb = *(const ulonglong2*)(frow + 4);
            ulonglong2 fc = *(const ulonglong2*)(frow + 8);
            ulonglong2 fd = *(const ulonglong2*)(frow + 12);
            ulonglong2 wa = *(const ulonglong2*)(wrow);
            ulonglong2 wb = *(const ulonglong2*)(wrow + 4);
            ulonglong2 wc = *(const ulonglong2*)(wrow + 256);
            ulonglong2 wd = *(const ulonglong2*)(wrow + 260);
            unsigned long long f[8]  = {fa.x, fa.y, fb.x, fb.y,
                                        fc.x, fc.y, fd.x, fd.y};
            unsigned long long wv[8] = {wa.x, wa.y, wb.x, wb.y,
                                        wc.x, wc.y, wd.x, wd.y};
            #pragma unroll
            for (int p = 0; p < 8; p++)
                #pragma unroll
                for (int j = 0; j < 8; j++)
                    FFMA2(acc[p][j], f[p], wv[j]);
        }

        // ---- epilogue: relu, gate, contract with W2, add gated b2 ----
        float  bb[8];
        float4 w2f[8];
        #pragma unroll
        for (int jj = 0; jj < 8; jj++) {
            int col = (jj < 4) ? (j0 + jj) : (128 + j0 + jj - 4);
            bb[jj]  = b1_s[col];
            w2f[jj] = *(const float4*)(w2_s + col * 4);
        }
        float bb2[4];
        #pragma unroll
        for (int o = 0; o < 4; o++) bb2[o] = __ldg(&b2[e * 4 + o]);

        #pragma unroll
        for (int p = 0; p < 8; p++) {
            float wpe = wgt_s[(p0 + p) * NEXP + e];
            if (lane == 0) {   // b2 term once per warp's hidden split
                #pragma unroll
                for (int o = 0; o < 4; o++)
                    acc_out[p][o] = fmaf(wpe, bb2[o], acc_out[p][o]);
            }
            #pragma unroll
            for (int jj = 0; jj < 8; jj++) {
                unsigned long long v = acc[p][jj];
                float lo = __uint_as_float((unsigned)(v & 0xffffffffu));
                float hi = __uint_as_float((unsigned)(v >> 32));
                float h = lo + hi + bb[jj];
                h = fmaxf(h, 0.0f) * wpe;
                acc_out[p][0] = fmaf(h, w2f[jj].x, acc_out[p][0]);
                acc_out[p][1] = fmaf(h, w2f[jj].y, acc_out[p][1]);
                acc_out[p][2] = fmaf(h, w2f[jj].z, acc_out[p][2]);
                acc_out[p][3] = fmaf(h, w2f[jj].w, acc_out[p][3]);
            }
        }
    }

    // ---- warp reduction across the 32-lane hidden split, lane 0 stores ----
    #pragma unroll
    for (int p = 0; p < 8; p++) {
        #pragma unroll
        for (int o = 0; o < 4; o++) {
            float v = acc_out[p][o];
            v += __shfl_xor_sync(0xffffffffu, v, 16);
            v += __shfl_xor_sync(0xffffffffu, v, 8);
            v += __shfl_xor_sync(0xffffffffu, v, 4);
            v += __shfl_xor_sync(0xffffffffu, v, 2);
            v += __shfl_xor_sync(0xffffffffu, v, 1);
            acc_out[p][o] = v;
        }
    }
    if (lane == 0) {
        #pragma unroll
        for (int p = 0; p < 8; p++) {
            float4 v = make_float4(acc_out[p][0], acc_out[p][1],
                                   acc_out[p][2], acc_out[p][3]);
            *(float4*)(out + (n0 + p0 + p) * DOUTS) = v;
        }
    }
}

extern "C" void kernel_launch(void* const* d_in, const int* in_sizes, int n_in,
                              void* d_out, int out_size)
{
    const float* x    = (const float*)d_in[0];
    const float* cent = (const float*)d_in[1];
    const float* W1   = (const float*)d_in[2];
    const float* b1   = (const float*)d_in[3];
    const float* W2   = (const float*)d_in[4];
    const float* b2   = (const float*)d_in[5];
    float* out = (float*)d_out;

    (void)in_sizes; (void)n_in; (void)out_size;

    cudaFuncSetAttribute(meganerf_kernel,
                         cudaFuncAttributeMaxDynamicSharedMemorySize, SMEM_BYTES);

    dim3 grid(NPTS / BM);
    dim3 block(NTHREADS);
    meganerf_kernel<<<grid, block, SMEM_BYTES>>>(x, cent, W1, b1, W2, b2, out);
}

// round 5
// speedup vs baseline: 1.2374x; 1.2374x over previous
#include <cuda_runtime.h>

// MegaNeRF MoE head: N=131072 points, E=8 experts, MLP 90 -> 256 -> 4,
// inverse-distance expert gating with margin cutoff.
//
// Round 4: fp32x2 packed-FMA kernel, BANK-CONFLICT-FREE smem layout.
//   vs round 3 (1498 us, L1=76% / fma=42.5% -> smem-bound):
//   - Main-loop W1 reads: lane l now owns column pairs {q*64+2l, q*64+2l+1}
//     (q=0..3). Each LDS.128 phase covers a contiguous 128B -> conflict-free
//     (was 2-way conflicted at stride 8 floats/lane).
//   - W1 staging: each thread assembles one 16B pair-interleaved chunk from
//     two float2 gmem loads and writes a single contiguous STS.128
//     (was 4x scattered STS.32 with ~8-way conflicts).

#define NPTS  131072
#define NEXP  8
#define DIN   90
#define HID   256
#define DOUTS 4
#define XCOLS 93
#define KP    (DIN / 2)          // 45 k-pairs

#define BM       64
#define NTHREADS 256
#define FS2      72              // feat row stride in float2 units (144 floats)

// smem layout (floats)
#define OFF_FEAT 0                                   // [KP][FS2*2] pair-interleaved
#define OFF_W1   (OFF_FEAT + KP * FS2 * 2)           // 6480 ; [KP][512] pair-interleaved
#define OFF_XYZ  (OFF_W1 + KP * HID * 2)             // +23040
#define OFF_WGT  (OFF_XYZ + BM * 4)                  // +256
#define OFF_B1   (OFF_WGT + BM * NEXP)               // +512
#define OFF_W2   (OFF_B1 + HID)                      // +256
#define SMEM_FLOATS (OFF_W2 + HID * DOUTS)           // +1024 = 31568 floats
#define SMEM_BYTES  (SMEM_FLOATS * 4)                // 126272 B

#define FFMA2(acc, a, b) \
    asm("fma.rn.f32x2 %0, %1, %2, %0;" : "+l"(acc) : "l"(a), "l"(b))

static __global__ void __launch_bounds__(NTHREADS, 1)
meganerf_kernel(const float* __restrict__ x,
                const float* __restrict__ cent,
                const float* __restrict__ W1,
                const float* __restrict__ b1,
                const float* __restrict__ W2,
                const float* __restrict__ b2,
                float* __restrict__ out)
{
    extern __shared__ float sm[];
    float* feat_s = sm + OFF_FEAT;   // feat_s[kp*144 + p*2 + parity]
    float* w1_s   = sm + OFF_W1;     // w1_s[kp*512 + 2*j + parity]
    float* xyz_s  = sm + OFF_XYZ;    // [BM][4]
    float* wgt_s  = sm + OFF_WGT;    // [BM][NEXP]
    float* b1_s   = sm + OFF_B1;     // [HID]
    float* w2_s   = sm + OFF_W2;     // [HID][4]

    const int tid  = threadIdx.x;
    const int lane = tid & 31;
    const int warp = tid >> 5;                 // 0..7  -> point group
    const long n0  = (long)blockIdx.x * BM;

    // ---- load x tile, coalesced; split xyz / pair-interleaved feat ----
    const float* xt = x + n0 * XCOLS;
    for (int i = tid; i < BM * XCOLS; i += NTHREADS) {
        float v = xt[i];
        int p = i / XCOLS;
        int c = i - p * XCOLS;
        if (c < 3) {
            xyz_s[p * 4 + c] = v;
        } else {
            int k = c - 3;                      // 0..89
            feat_s[(k >> 1) * (FS2 * 2) + p * 2 + (k & 1)] = v;
        }
    }
    __syncthreads();

    // ---- per-point gating weights (one thread per point) ----
    if (tid < BM) {
        float px = xyz_s[tid * 4 + 0];
        float py = xyz_s[tid * 4 + 1];
        float pz = xyz_s[tid * 4 + 2];
        float d[NEXP];
        float mind = 3.402823466e38f;
        #pragma unroll
        for (int e = 0; e < NEXP; e++) {
            float dx = px - cent[e * 3 + 0];
            float dy = py - cent[e * 3 + 1];
            float dz = pz - cent[e * 3 + 2];
            float dd = sqrtf(dx * dx + dy * dy + dz * dz);
            d[e] = dd;
            mind = fminf(mind, dd);
        }
        float thr = 2.0f * mind;
        float inv[NEXP];
        float s = 0.0f;
        #pragma unroll
        for (int e = 0; e < NEXP; e++) {
            float iv = (d[e] > thr) ? 0.0f : 1.0f / (d[e] + 1e-8f);
            inv[e] = iv;
            s += iv;
        }
        float rs = 1.0f / s;
        #pragma unroll
        for (int e = 0; e < NEXP; e++) wgt_s[tid * NEXP + e] = inv[e] * rs;
    }

    const int p0 = warp * 8;       // this warp's 8 points
    // lane owns hidden column pairs {q*64 + 2*lane, q*64 + 2*lane + 1}, q=0..3

    float acc_out[8][4];
    #pragma unroll
    for (int p = 0; p < 8; p++)
        #pragma unroll
        for (int o = 0; o < 4; o++) acc_out[p][o] = 0.0f;

    for (int e = 0; e < NEXP; e++) {
        __syncthreads();   // protect w1_s/b1_s/w2_s readers of previous iter

        // ---- stage W1[e] pair-interleaved, conflict-free STS.128 ----
        // chunk cu -> (m = cu>>7, u = cu&127): rows 2m,2m+1, cols 2u,2u+1.
        // One 16B chunk at w1_s + m*512 + 4u, consecutive threads contiguous.
        const float* w1g = W1 + (size_t)e * DIN * HID;
        for (int cu = tid; cu < KP * 128; cu += NTHREADS) {
            int m = cu >> 7;
            int u = cu & 127;
            float2 a = *(const float2*)(w1g + (2 * m)     * HID + 2 * u);
            float2 b = *(const float2*)(w1g + (2 * m + 1) * HID + 2 * u);
            *(float4*)(w1_s + m * 512 + 4 * u) = make_float4(a.x, b.x, a.y, b.y);
        }
        for (int i = tid; i < HID; i += NTHREADS)
            b1_s[i] = b1[e * HID + i];
        for (int i = tid; i < HID * DOUTS; i += NTHREADS)
            w2_s[i] = W2[e * HID * DOUTS + i];
        __syncthreads();

        // ---- main GEMM fragment: 8 points x 8 hidden cols, K=90 as 45 pairs ----
        unsigned long long acc[8][8];
        #pragma unroll
        for (int p = 0; p < 8; p++)
            #pragma unroll
            for (int j = 0; j < 8; j++) acc[p][j] = 0ULL;

        const float* frow = feat_s + p0 * 2;
        const float* wrow = w1_s + 4 * lane;
        #pragma unroll 3
        for (int kp = 0; kp < KP; kp++, frow += FS2 * 2, wrow += HID * 2) {
            ulonglong2 fa = *(const ulonglong2*)(frow);
            ulonglong2 fb = *(const ulonglong2*)(frow + 4);
            ulonglong2 fc = *(const ulonglong2*)(frow + 8);
            ulonglong2 fd = *(const ulonglong2*)(frow + 12);
            ulonglong2 wa = *(const ulonglong2*)(wrow);          // cols 2l, 2l+1
            ulonglong2 wb = *(const ulonglong2*)(wrow + 128);    // cols 64+2l, ...
            ulonglong2 wc = *(const ulonglong2*)(wrow + 256);    // cols 128+2l, ...
            ulonglong2 wd = *(const ulonglong2*)(wrow + 384);    // cols 192+2l, ...
            unsigned long long f[8]  = {fa.x, fa.y, fb.x, fb.y,
                                        fc.x, fc.y, fd.x, fd.y};
            unsigned long long wv[8] = {wa.x, wa.y, wb.x, wb.y,
                                        wc.x, wc.y, wd.x, wd.y};
            #pragma unroll
            for (int p = 0; p < 8; p++)
                #pragma unroll
                for (int j = 0; j < 8; j++)
                    FFMA2(acc[p][j], f[p], wv[j]);
        }

        // ---- epilogue: relu, gate, contract with W2, add gated b2 ----
        float  bb[8];
        float4 w2f[8];
        #pragma unroll
        for (int jj = 0; jj < 8; jj++) {
            int col = (jj >> 1) * 64 + 2 * lane + (jj & 1);
            bb[jj]  = b1_s[col];
            w2f[jj] = *(const float4*)(w2_s + col * 4);
        }
        float bb2[4];
        #pragma unroll
        for (int o = 0; o < 4; o++) bb2[o] = __ldg(&b2[e * 4 + o]);

        #pragma unroll
        for (int p = 0; p < 8; p++) {
            float wpe = wgt_s[(p0 + p) * NEXP + e];
            if (lane == 0) {   // b2 term once per warp's hidden split
                #pragma unroll
                for (int o = 0; o < 4; o++)
                    acc_out[p][o] = fmaf(wpe, bb2[o], acc_out[p][o]);
            }
            #pragma unroll
            for (int jj = 0; jj < 8; jj++) {
                unsigned long long v = acc[p][jj];
                float lo = __uint_as_float((unsigned)(v & 0xffffffffu));
                float hi = __uint_as_float((unsigned)(v >> 32));
                float h = lo + hi + bb[jj];
                h = fmaxf(h, 0.0f) * wpe;
                acc_out[p][0] = fmaf(h, w2f[jj].x, acc_out[p][0]);
                acc_out[p][1] = fmaf(h, w2f[jj].y, acc_out[p][1]);
                acc_out[p][2] = fmaf(h, w2f[jj].z, acc_out[p][2]);
                acc_out[p][3] = fmaf(h, w2f[jj].w, acc_out[p][3]);
            }
        }
    }

    // ---- warp reduction across the 32-lane hidden split, lane 0 stores ----
    #pragma unroll
    for (int p = 0; p < 8; p++) {
        #pragma unroll
        for (int o = 0; o < 4; o++) {
            float v = acc_out[p][o];
            v += __shfl_xor_sync(0xffffffffu, v, 16);
            v += __shfl_xor_sync(0xffffffffu, v, 8);
            v += __shfl_xor_sync(0xffffffffu, v, 4);
            v += __shfl_xor_sync(0xffffffffu, v, 2);
            v += __shfl_xor_sync(0xffffffffu, v, 1);
            acc_out[p][o] = v;
        }
    }
    if (lane == 0) {
        #pragma unroll
        for (int p = 0; p < 8; p++) {
            float4 v = make_float4(acc_out[p][0], acc_out[p][1],
                                   acc_out[p][2], acc_out[p][3]);
            *(float4*)(out + (n0 + p0 + p) * DOUTS) = v;
        }
    }
}

extern "C" void kernel_launch(void* const* d_in, const int* in_sizes, int n_in,
                              void* d_out, int out_size)
{
    const float* x    = (const float*)d_in[0];
    const float* cent = (const float*)d_in[1];
    const float* W1   = (const float*)d_in[2];
    const float* b1   = (const float*)d_in[3];
    const float* W2   = (const float*)d_in[4];
    const float* b2   = (const float*)d_in[5];
    float* out = (float*)d_out;

    (void)in_sizes; (void)n_in; (void)out_size;

    cudaFuncSetAttribute(meganerf_kernel,
                         cudaFuncAttributeMaxDynamicSharedMemorySize, SMEM_BYTES);

    dim3 grid(NPTS / BM);
    dim3 block(NTHREADS);
    meganerf_kernel<<<grid, block, SMEM_BYTES>>>(x, cent, W1, b1, W2, b2, out);
}

// round 9
// speedup vs baseline: 2.5058x; 2.0252x over previous
#include <cuda_runtime.h>
#include <cuda_bf16.h>
#include <cstdint>

// MegaNeRF MoE head via mma.sync (HMMA) bf16 3-split — portable to the
// harness's non-'a' compute_103 target (tcgen05 is rejected by its ptxas).
//
// D = A*B with A = feat (128 x 96pad), B = W1^T (96 x 256), fp32 accum, and
// Markidis split: Ahi*Bhi + Ahi*Blo + Alo*Bhi  (residual ~2^-18).
//
// prep_kernel: converts W1 once into fragment-major hi/lo bf16 pairs in a
// __device__ global (786 KB). main kernel copies per-expert B frags to smem
// (98 KB) and runs 8 warps (2M x 4N, warp tile 64x64) of m16n8k16 mma.

#define NPTS   131072
#define NEXP   8
#define DIN    90
#define HID    256
#define XCOLS  93
#define BM     128
#define NTH    256
#define NKS    6                      // k-steps of 16 (K=96 padded)
#define NTILES 32                     // 256 / 8
#define MTILES 8                      // 128 / 16
#define FRAG_B_U32 (NTILES * NKS * 64)    // 12288 u32 per split
#define FRAG_A_U32 (MTILES * NKS * 128)   // 6144  u32 per split

__device__ uint32_t g_w1frag[NEXP][2][FRAG_B_U32];   // [expert][hi/lo][frag]

// ---- smem byte offsets ----
#define SO_WGT 0                                   // 128*8 f32 = 4096
#define SO_B1  (SO_WGT + 4096)                     // 256 f32
#define SO_W2  (SO_B1 + 1024)                      // 256*4 f32
#define SO_RED (SO_W2 + 4096)                      // 128*4 f32
#define SO_A   (SO_RED + 2048)                     // 2*6144*4  = 49152
#define SO_B   (SO_A + 2 * FRAG_A_U32 * 4)         // 2*12288*4 = 98304
#define SO_X   SO_B                                // x tile aliases B (pre-loop)
#define SMEM_BYTES (SO_B + 2 * FRAG_B_U32 * 4)     // 158720 B

// ---- prep: W1 -> fragment-major bf16 hi/lo ----
static __global__ void prep_kernel(const float* __restrict__ W1) {
    int gid = blockIdx.x * blockDim.x + threadIdx.x;
    if (gid >= NEXP * FRAG_B_U32) return;
    int e   = gid / FRAG_B_U32;
    int f   = gid % FRAG_B_U32;
    int nt  = f / (NKS * 64);
    int rem = f % (NKS * 64);
    int ks  = rem >> 6;
    int l2  = rem & 63;
    int lane = l2 >> 1, reg = l2 & 1;
    int n  = nt * 8 + (lane >> 2);
    int k0 = ks * 16 + (lane & 3) * 2 + reg * 8;
    const float* w = W1 + (size_t)e * DIN * HID;
    float v0 = (k0     < DIN) ? __ldg(w + k0 * HID + n)       : 0.0f;
    float v1 = (k0 + 1 < DIN) ? __ldg(w + (k0 + 1) * HID + n) : 0.0f;
    __nv_bfloat16 h0 = __float2bfloat16(v0), h1 = __float2bfloat16(v1);
    __nv_bfloat16 l0 = __float2bfloat16(v0 - __bfloat162float(h0));
    __nv_bfloat16 l1 = __float2bfloat16(v1 - __bfloat162float(h1));
    g_w1frag[e][0][f] = (uint32_t)__bfloat16_as_ushort(h0)
                      | ((uint32_t)__bfloat16_as_ushort(h1) << 16);
    g_w1frag[e][1][f] = (uint32_t)__bfloat16_as_ushort(l0)
                      | ((uint32_t)__bfloat16_as_ushort(l1) << 16);
}

__device__ __forceinline__ void mma16816(float* d, const uint32_t* a,
                                         const uint32_t* b) {
    asm volatile(
        "mma.sync.aligned.m16n8k16.row.col.f32.bf16.bf16.f32 "
        "{%0,%1,%2,%3}, {%4,%5,%6,%7}, {%8,%9}, {%0,%1,%2,%3};"
        : "+f"(d[0]), "+f"(d[1]), "+f"(d[2]), "+f"(d[3])
        : "r"(a[0]), "r"(a[1]), "r"(a[2]), "r"(a[3]), "r"(b[0]), "r"(b[1]));
}

static __global__ void __launch_bounds__(NTH, 1)
meganerf_mma_kernel(const float* __restrict__ x,
                    const float* __restrict__ cent,
                    const float* __restrict__ b1,
                    const float* __restrict__ W2,
                    const float* __restrict__ b2,
                    float* __restrict__ out)
{
    extern __shared__ char smem[];
    float*    wgt_s = (float*)(smem + SO_WGT);
    float*    b1_s  = (float*)(smem + SO_B1);
    float*    w2_s  = (float*)(smem + SO_W2);
    float*    red_s = (float*)(smem + SO_RED);
    uint32_t* As    = (uint32_t*)(smem + SO_A);
    uint32_t* Bs    = (uint32_t*)(smem + SO_B);
    float*    xs    = (float*)(smem + SO_X);     // [128][96], aliases Bs

    const int tid    = threadIdx.x;
    const int lane   = tid & 31;
    const int wid    = tid >> 5;
    const int warp_m = wid & 1;        // rows 64*warp_m .. +64
    const int warp_n = wid >> 1;       // cols 64*warp_n .. +64
    const long n0    = (long)blockIdx.x * BM;

    // ---- stage x tile coalesced into xs [128][96] ----
    const float* xt = x + n0 * XCOLS;
    for (int i = tid; i < BM * XCOLS; i += NTH) {
        int p = i / XCOLS, c = i - p * XCOLS;
        xs[p * 96 + c] = __ldg(xt + i);
    }
    for (int i = tid; i < BM * 4; i += NTH) red_s[i] = 0.0f;
    __syncthreads();

    // ---- gating weights (threads 0..127, one point each) ----
    if (tid < BM) {
        float px = xs[tid * 96 + 0], py = xs[tid * 96 + 1], pz = xs[tid * 96 + 2];
        float d[NEXP], mind = 3.402823466e38f;
        #pragma unroll
        for (int e = 0; e < NEXP; e++) {
            float dx = px - __ldg(&cent[e * 3 + 0]);
            float dy = py - __ldg(&cent[e * 3 + 1]);
            float dz = pz - __ldg(&cent[e * 3 + 2]);
            float dd = sqrtf(dx * dx + dy * dy + dz * dz);
            d[e] = dd; mind = fminf(mind, dd);
        }
        float thr = 2.0f * mind, s = 0.0f, inv[NEXP];
        #pragma unroll
        for (int e = 0; e < NEXP; e++) {
            float iv = (d[e] > thr) ? 0.0f : 1.0f / (d[e] + 1e-8f);
            inv[e] = iv; s += iv;
        }
        float rs = 1.0f / s;
        #pragma unroll
        for (int e = 0; e < NEXP; e++) wgt_s[tid * NEXP + e] = inv[e] * rs;
    }

    // ---- build A fragments (hi/lo) from xs ----
    for (int f = tid; f < FRAG_A_U32; f += NTH) {
        int mt  = f / (NKS * 128);
        int rem = f % (NKS * 128);
        int ks  = rem >> 7;
        int l2  = rem & 127;
        int lf  = l2 >> 2, rg = l2 & 3;
        int row = mt * 16 + (lf >> 2) + (rg & 1) * 8;
        int k0  = ks * 16 + (lf & 3) * 2 + (rg >> 1) * 8;
        float v0 = (k0     < DIN) ? xs[row * 96 + 3 + k0]     : 0.0f;
        float v1 = (k0 + 1 < DIN) ? xs[row * 96 + 3 + k0 + 1] : 0.0f;
        __nv_bfloat16 h0 = __float2bfloat16(v0), h1 = __float2bfloat16(v1);
        __nv_bfloat16 l0 = __float2bfloat16(v0 - __bfloat162float(h0));
        __nv_bfloat16 l1 = __float2bfloat16(v1 - __bfloat162float(h1));
        uint32_t hp = (uint32_t)__bfloat16_as_ushort(h0)
                    | ((uint32_t)__bfloat16_as_ushort(h1) << 16);
        uint32_t lp = (uint32_t)__bfloat16_as_ushort(l0)
                    | ((uint32_t)__bfloat16_as_ushort(l1) << 16);
        // NOTE: As read happens after the next __syncthreads; xs alias is only
        // overwritten by the B copy of expert 0, which is also after that sync.
        As[f]               = hp;
        As[FRAG_A_U32 + f]  = lp;
    }

    float acc_out[8][4];
    #pragma unroll
    for (int i = 0; i < 8; i++)
        #pragma unroll
        for (int o = 0; o < 4; o++) acc_out[i][o] = 0.0f;

    for (int e = 0; e < NEXP; e++) {
        __syncthreads();   // prior readers of Bs/b1_s/w2_s (and xs) done

        // ---- copy B fragments (hi+lo, 98 KB) from global scratch ----
        {
            const uint4* src = (const uint4*)&g_w1frag[e][0][0];
            uint4* dst = (uint4*)Bs;
            #pragma unroll 4
            for (int i = tid; i < (2 * FRAG_B_U32) / 4; i += NTH)
                dst[i] = __ldg(src + i);
        }
        for (int i = tid; i < HID; i += NTH) b1_s[i] = __ldg(&b1[e * HID + i]);
        for (int i = tid; i < HID * 4; i += NTH)
            w2_s[i] = __ldg(&W2[e * HID * 4 + i]);
        __syncthreads();

        // ---- 3-split mma: acc[4 mt][8 nt][4] fp32 ----
        float acc[4][8][4];
        #pragma unroll
        for (int m = 0; m < 4; m++)
            #pragma unroll
            for (int n = 0; n < 8; n++)
                #pragma unroll
                for (int r = 0; r < 4; r++) acc[m][n][r] = 0.0f;

        #pragma unroll
        for (int t = 0; t < 3; t++) {
            const int sA = (t == 2) ? 1 : 0;
            const int sB = (t == 1) ? 1 : 0;
            const uint32_t* Ab = As + sA * FRAG_A_U32;
            const uint32_t* Bb = Bs + sB * FRAG_B_U32;
            #pragma unroll
            for (int ks = 0; ks < NKS; ks++) {
                uint32_t a[4][4], b[8][2];
                #pragma unroll
                for (int m = 0; m < 4; m++)
                    *(uint4*)a[m] = *(const uint4*)(Ab
                        + ((warp_m * 4 + m) * NKS + ks) * 128 + lane * 4);
                #pragma unroll
                for (int n = 0; n < 8; n++)
                    *(uint2*)b[n] = *(const uint2*)(Bb
                        + ((warp_n * 8 + n) * NKS + ks) * 64 + lane * 2);
                #pragma unroll
                for (int m = 0; m < 4; m++)
                    #pragma unroll
                    for (int n = 0; n < 8; n++)
                        mma16816(acc[m][n], a[m], b[n]);
            }
        }

        // ---- epilogue: bias+relu+gate, contract with W2 into acc_out ----
        #pragma unroll
        for (int m = 0; m < 4; m++) {
            int r0 = warp_m * 64 + m * 16 + (lane >> 2);
            float wp0 = wgt_s[r0 * NEXP + e];
            float wp1 = wgt_s[(r0 + 8) * NEXP + e];
            #pragma unroll
            for (int n = 0; n < 8; n++) {
                int c0 = warp_n * 64 + n * 8 + (lane & 3) * 2;
                float bc0 = b1_s[c0], bc1 = b1_s[c0 + 1];
                float4 w20 = *(const float4*)(w2_s + c0 * 4);
                float4 w21 = *(const float4*)(w2_s + (c0 + 1) * 4);
                float* A = acc[m][n];
                float h00 = fmaxf(A[0] + bc0, 0.0f) * wp0;
                float h01 = fmaxf(A[1] + bc1, 0.0f) * wp0;
                float h10 = fmaxf(A[2] + bc0, 0.0f) * wp1;
                float h11 = fmaxf(A[3] + bc1, 0.0f) * wp1;
                float* o0 = acc_out[m * 2];
                float* o1 = acc_out[m * 2 + 1];
                o0[0] = fmaf(h00, w20.x, fmaf(h01, w21.x, o0[0]));
                o0[1] = fmaf(h00, w20.y, fmaf(h01, w21.y, o0[1]));
                o0[2] = fmaf(h00, w20.z, fmaf(h01, w21.z, o0[2]));
                o0[3] = fmaf(h00, w20.w, fmaf(h01, w21.w, o0[3]));
                o1[0] = fmaf(h10, w20.x, fmaf(h11, w21.x, o1[0]));
                o1[1] = fmaf(h10, w20.y, fmaf(h11, w21.y, o1[1]));
                o1[2] = fmaf(h10, w20.z, fmaf(h11, w21.z, o1[2]));
                o1[3] = fmaf(h10, w20.w, fmaf(h11, w21.w, o1[3]));
            }
        }
    }

    // ---- reduce over the 4 lanes sharing a row, then across warp_n ----
    #pragma unroll
    for (int i = 0; i < 8; i++)
        #pragma unroll
        for (int o = 0; o < 4; o++) {
            float v = acc_out[i][o];
            v += __shfl_xor_sync(0xffffffffu, v, 1);
            v += __shfl_xor_sync(0xffffffffu, v, 2);
            acc_out[i][o] = v;
        }
    if ((lane & 3) == 0) {
        #pragma unroll
        for (int m = 0; m < 4; m++) {
            #pragma unroll
            for (int h = 0; h < 2; h++) {
                int row = warp_m * 64 + m * 16 + (lane >> 2) + h * 8;
                #pragma unroll
                for (int o = 0; o < 4; o++)
                    atomicAdd(&red_s[row * 4 + o], acc_out[m * 2 + h][o]);
            }
        }
    }
    __syncthreads();

    if (tid < BM) {
        float4 v = *(const float4*)(red_s + tid * 4);
        #pragma unroll
        for (int e = 0; e < NEXP; e++) {
            float wpe = wgt_s[tid * NEXP + e];
            v.x = fmaf(wpe, __ldg(&b2[e * 4 + 0]), v.x);
            v.y = fmaf(wpe, __ldg(&b2[e * 4 + 1]), v.y);
            v.z = fmaf(wpe, __ldg(&b2[e * 4 + 2]), v.z);
            v.w = fmaf(wpe, __ldg(&b2[e * 4 + 3]), v.w);
        }
        *(float4*)(out + (n0 + tid) * 4) = v;
    }
}

extern "C" void kernel_launch(void* const* d_in, const int* in_sizes, int n_in,
                              void* d_out, int out_size)
{
    const float* x    = (const float*)d_in[0];
    const float* cent = (const float*)d_in[1];
    const float* W1   = (const float*)d_in[2];
    const float* b1   = (const float*)d_in[3];
    const float* W2   = (const float*)d_in[4];
    const float* b2   = (const float*)d_in[5];
    float* out = (float*)d_out;
    (void)in_sizes; (void)n_in; (void)out_size;

    prep_kernel<<<(NEXP * FRAG_B_U32 + NTH - 1) / NTH, NTH>>>(W1);

    cudaFuncSetAttribute(meganerf_mma_kernel,
                         cudaFuncAttributeMaxDynamicSharedMemorySize, SMEM_BYTES);
    meganerf_mma_kernel<<<NPTS / BM, NTH, SMEM_BYTES>>>(x, cent, b1, W2, b2, out);
}